// round 3
// baseline (speedup 1.0000x reference)
#include <cuda_runtime.h>
#include <cuda_bf16.h>
#include <cmath>

// Problem constants (fixed by setup_inputs):
//   x: (4, 16384, 512) fp32, w_qkv: (512,1536), b_qkv: (1536,)
//   w_proj: (512,512), b_proj: (512,), height=width=128, heads=8, hd=64
#define BATCH 4
#define SEQ   16384
#define CDIM  512
#define HEADS 8
#define HD    64
#define MTOT  (BATCH*SEQ)        // 65536
#define N1    1536
#define N2    512

// ---------------- scratch (device globals; no allocations allowed) ----------
__device__ float g_qkv[(long)MTOT * N1];     // post-rope/elu qkv, natural GEMM layout
__device__ float g_attn[(long)MTOT * N2];    // attention output pre-projection
__device__ float g_kvp[2048 * 4096];         // per-chunk KV partials (32 bh * 64 chunks)
__device__ float g_ksp[2048 * 64];           // per-chunk ksum partials
__device__ float g_kv[32 * 4096];            // reduced KV per (b,h)
__device__ float g_ksum[32 * 64];            // reduced ksum per (b,h)
__device__ float g_tab[4096];                // [0..2047]=cos(t*freq_i), [2048..4095]=sin

// ---------------- helpers ----------------
__device__ __forceinline__ float elu1(float u) {
    return u > 0.0f ? u + 1.0f : __expf(u);
}

// ---------------- table init ----------------
__global__ void init_tables() {
    int id = blockIdx.x * blockDim.x + threadIdx.x;
    if (id < 2048) {
        int t = id >> 4;
        int i = id & 15;
        // freqs[i] = theta^(-4i/hd) = 10^(-i/16); compute in double for accuracy
        double freq = pow(10.0, -(double)i / 16.0);
        double ang = (double)t * freq;
        g_tab[id]        = (float)cos(ang);
        g_tab[2048 + id] = (float)sin(ang);
    }
}

// ---------------- SGEMM 128x128x8, 256 threads, 8x8 per thread ----------------
// FUSED=true: qkv GEMM -> bias, axial rope, elu+1 fused epilogue, writes C (=g_qkv)
// FUSED=false: plain bias epilogue
template<int N, bool FUSED>
__global__ __launch_bounds__(256)
void sgemm(const float* __restrict__ A, const float* __restrict__ B,
           const float* __restrict__ bias, float* __restrict__ C) {
    __shared__ __align__(16) float As[8 * 128];
    __shared__ __align__(16) float Bs[8 * 128];

    const int tid = threadIdx.x;
    const int rowBlock = blockIdx.y * 128;
    const int colBlock = blockIdx.x * 128;

    const int aRow = tid >> 1;            // 0..127
    const int aCol = (tid & 1) * 4;       // 0 or 4
    const int bRow = tid >> 5;            // 0..7
    const int bCol = (tid & 31) * 4;      // 0..124

    const float* Ap = A + (long)(rowBlock + aRow) * CDIM + aCol;
    const float* Bp = B + (long)bRow * N + colBlock + bCol;

    float acc[8][8];
#pragma unroll
    for (int i = 0; i < 8; i++)
#pragma unroll
        for (int j = 0; j < 8; j++) acc[i][j] = 0.0f;

    const int ty = tid >> 4;   // 0..15
    const int tx = tid & 15;   // 0..15

    for (int kt = 0; kt < CDIM; kt += 8) {
        float4 a  = *(const float4*)(Ap + kt);
        float4 bb = *(const float4*)(Bp + (long)kt * N);
        As[(aCol + 0) * 128 + aRow] = a.x;
        As[(aCol + 1) * 128 + aRow] = a.y;
        As[(aCol + 2) * 128 + aRow] = a.z;
        As[(aCol + 3) * 128 + aRow] = a.w;
        *(float4*)&Bs[bRow * 128 + bCol] = bb;
        __syncthreads();

#pragma unroll
        for (int k = 0; k < 8; k++) {
            float ra[8], rb[8];
            *(float4*)&ra[0] = *(const float4*)&As[k * 128 + ty * 8];
            *(float4*)&ra[4] = *(const float4*)&As[k * 128 + ty * 8 + 4];
            *(float4*)&rb[0] = *(const float4*)&Bs[k * 128 + tx * 8];
            *(float4*)&rb[4] = *(const float4*)&Bs[k * 128 + tx * 8 + 4];
#pragma unroll
            for (int i = 0; i < 8; i++)
#pragma unroll
                for (int j = 0; j < 8; j++)
                    acc[i][j] += ra[i] * rb[j];
        }
        __syncthreads();
    }

    // -------- epilogue --------
    const int c0 = colBlock + tx * 8;
    float bv[8];
#pragma unroll
    for (int j = 0; j < 8; j++) bv[j] = bias[c0 + j];

    bool plain = true;
    if (FUSED) plain = ((c0 >> 9) == 2);   // v part: no rope/elu (uniform per block)

    if (plain) {
#pragma unroll
        for (int i = 0; i < 8; i++) {
            int row = rowBlock + ty * 8 + i;
            float4 o1, o2;
            o1.x = acc[i][0] + bv[0]; o1.y = acc[i][1] + bv[1];
            o1.z = acc[i][2] + bv[2]; o1.w = acc[i][3] + bv[3];
            o2.x = acc[i][4] + bv[4]; o2.y = acc[i][5] + bv[5];
            o2.z = acc[i][6] + bv[6]; o2.w = acc[i][7] + bv[7];
            *(float4*)&C[(long)row * N + c0]     = o1;
            *(float4*)&C[(long)row * N + c0 + 4] = o2;
        }
    } else {
        const int d0 = c0 & 63;           // dim within head; block never straddles heads
        const int half = d0 >> 5;         // 0: x-angles, 1: y-angles
        const int ibase = (d0 & 31) >> 1; // freq index base
#pragma unroll
        for (int i = 0; i < 8; i++) {
            int row = rowBlock + ty * 8 + i;
            int n = row & (SEQ - 1);
            int t = half ? (n >> 7) : (n & 127);
            const float* cp = g_tab + t * 16 + ibase;
            float o[8];
#pragma unroll
            for (int p = 0; p < 4; p++) {
                float cc = cp[p];
                float ss = cp[2048 + p];
                float xr = acc[i][2 * p]     + bv[2 * p];
                float xi = acc[i][2 * p + 1] + bv[2 * p + 1];
                float orr = xr * cc - xi * ss;
                float oii = xr * ss + xi * cc;
                o[2 * p]     = elu1(orr);
                o[2 * p + 1] = elu1(oii);
            }
            *(float4*)&C[(long)row * N + c0]     = *(float4*)&o[0];
            *(float4*)&C[(long)row * N + c0 + 4] = *(float4*)&o[4];
        }
    }
}

// ---------------- KV / ksum partial reduction ----------------
// grid: (64 chunks, 32 bh), 256 threads. Each block reduces 256 tokens.
__global__ __launch_bounds__(256)
void kv_partial() {
    const int chunk = blockIdx.x;
    const int bh = blockIdx.y;
    const int b = bh >> 3, h = bh & 7;
    const int tid = threadIdx.x;
    const int d  = tid & 63;
    const int e0 = (tid >> 6) << 4;      // uniform within a warp
    const int lr = tid >> 6;             // load row within 4-group
    const int ld = tid & 63;

    __shared__ float ks[4][64];
    __shared__ float vs[4][64];

    float acc[16];
#pragma unroll
    for (int e = 0; e < 16; e++) acc[e] = 0.0f;
    float ksacc = 0.0f;

    const long base = (long)(b * SEQ + chunk * 256) * N1 + h * HD;
    const float* Kp = g_qkv + base + 512;
    const float* Vp = g_qkv + base + 1024;

    for (int g = 0; g < 256; g += 4) {
        ks[lr][ld] = Kp[(long)(g + lr) * N1 + ld];
        vs[lr][ld] = Vp[(long)(g + lr) * N1 + ld];
        __syncthreads();
#pragma unroll
        for (int r = 0; r < 4; r++) {
            float kd = ks[r][d];
            if (tid < 64) ksacc += kd;
            const float* vr = &vs[r][e0];
#pragma unroll
            for (int e = 0; e < 16; e++) acc[e] += kd * vr[e];
        }
        __syncthreads();
    }

    float* out = g_kvp + ((long)(bh * 64 + chunk)) * 4096 + d * 64 + e0;
#pragma unroll
    for (int e = 0; e < 16; e++) out[e] = acc[e];
    if (tid < 64) g_ksp[(bh * 64 + chunk) * 64 + tid] = ksacc;
}

// ---------------- final reduce of partials (deterministic) ----------------
__global__ void kv_reduce() {
    int gid = blockIdx.x * 256 + threadIdx.x;
    if (gid < 32 * 4096) {
        int bh = gid >> 12;
        int rem = gid & 4095;
        const float* p = g_kvp + (long)bh * 64 * 4096 + rem;
        float s = 0.0f;
#pragma unroll 8
        for (int c = 0; c < 64; c++) s += p[(long)c * 4096];
        g_kv[gid] = s;
    } else {
        int idx = gid - 32 * 4096;
        if (idx < 2048) {
            int bh = idx >> 6, dd = idx & 63;
            const float* p = g_ksp + bh * 64 * 64 + dd;
            float s = 0.0f;
#pragma unroll 8
            for (int c = 0; c < 64; c++) s += p[c * 64];
            g_ksum[idx] = s;
        }
    }
}

// ---------------- apply: out = (q @ KV) * 1/(q.ksum + 1e-6) ----------------
// grid: (64 chunks, 32 bh), 256 threads; one thread per token.
__global__ __launch_bounds__(256)
void apply_kernel() {
    const int chunk = blockIdx.x;
    const int bh = blockIdx.y;
    const int b = bh >> 3, h = bh & 7;
    const int tid = threadIdx.x;

    __shared__ float kv_sh[4096];
    __shared__ float ks_sh[64];
    for (int i = tid; i < 4096; i += 256) kv_sh[i] = g_kv[bh * 4096 + i];
    if (tid < 64) ks_sh[tid] = g_ksum[bh * 64 + tid];
    __syncthreads();

    const int n = chunk * 256 + tid;
    const float* qp = g_qkv + (long)(b * SEQ + n) * N1 + h * HD;
    float q[64];
#pragma unroll
    for (int i = 0; i < 16; i++)
        *(float4*)&q[i * 4] = *(const float4*)&qp[i * 4];

    float denom = 0.0f;
#pragma unroll
    for (int d = 0; d < 64; d++) denom += q[d] * ks_sh[d];
    float z = 1.0f / (denom + 1e-6f);

    float* op = g_attn + (long)(b * SEQ + n) * N2 + h * HD;
#pragma unroll
    for (int eh = 0; eh < 64; eh += 32) {
        float o[32];
#pragma unroll
        for (int e = 0; e < 32; e++) o[e] = 0.0f;
#pragma unroll 4
        for (int d = 0; d < 64; d++) {
            float qd = q[d];
            const float* kr = &kv_sh[d * 64 + eh];
#pragma unroll
            for (int e = 0; e < 32; e++) o[e] += qd * kr[e];
        }
#pragma unroll
        for (int e = 0; e < 32; e += 4) {
            float4 v4;
            v4.x = o[e] * z; v4.y = o[e + 1] * z;
            v4.z = o[e + 2] * z; v4.w = o[e + 3] * z;
            *(float4*)&op[eh + e] = v4;
        }
    }
}

// ---------------- launch ----------------
extern "C" void kernel_launch(void* const* d_in, const int* in_sizes, int n_in,
                              void* d_out, int out_size) {
    (void)in_sizes; (void)n_in; (void)out_size;
    const float* x      = (const float*)d_in[0];
    const float* w_qkv  = (const float*)d_in[1];
    const float* b_qkv  = (const float*)d_in[2];
    const float* w_proj = (const float*)d_in[3];
    const float* b_proj = (const float*)d_in[4];
    float* out = (float*)d_out;

    float* p_qkv = nullptr;
    float* p_attn = nullptr;
    cudaGetSymbolAddress((void**)&p_qkv, g_qkv);
    cudaGetSymbolAddress((void**)&p_attn, g_attn);

    init_tables<<<8, 256>>>();

    // QKV GEMM + bias + rope + elu+1 fused
    sgemm<N1, true><<<dim3(N1 / 128, MTOT / 128), 256>>>(x, w_qkv, b_qkv, p_qkv);

    // KV / ksum reduction (two-phase, deterministic)
    kv_partial<<<dim3(64, 32), 256>>>();
    kv_reduce<<<520, 256>>>();

    // apply attention
    apply_kernel<<<dim3(64, 32), 256>>>();

    // projection GEMM + bias
    sgemm<N2, false><<<dim3(N2 / 128, MTOT / 128), 256>>>(p_attn, w_proj, b_proj, out);
}

// round 10
// speedup vs baseline: 2.8828x; 2.8828x over previous
#include <cuda_runtime.h>
#include <cuda_bf16.h>
#include <cstdint>
#include <cmath>

// Problem constants (fixed by setup_inputs):
//   x: (4, 16384, 512) fp32, w_qkv: (512,1536), b_qkv: (1536,)
//   w_proj: (512,512), b_proj: (512,), height=width=128, heads=8, hd=64
#define BATCH 4
#define SEQ   16384
#define CDIM  512
#define MTOT  (BATCH*SEQ)        // 65536
#define N1    1536
#define N2    512

// ---------------- scratch (device globals; no allocations allowed) ----------
__device__ float g_qkv[(long)MTOT * N1];     // post-rope/elu qkv
__device__ float g_attn[(long)MTOT * N2];    // attention output pre-projection
__device__ float g_kvp[2048 * 4096];         // per-chunk KV partials
__device__ float g_ksp[2048 * 64];           // per-chunk ksum partials
__device__ float g_kv[32 * 4096];            // reduced KV per (b,h)
__device__ float g_ksum[32 * 64];            // reduced ksum per (b,h)
__device__ float g_tab[4096];                // [0..2047]=cos, [2048..4095]=sin
__device__ float g_bt1[(long)N1 * CDIM];     // w_qkv transposed: [N1, K]
__device__ float g_bt2[(long)N2 * CDIM];     // w_proj transposed: [N2, K]

// ============================ PTX helpers ===================================
__device__ __forceinline__ uint32_t smem_to_u32(const void* p) {
    uint32_t a;
    asm("{ .reg .u64 t; cvta.to.shared.u64 t, %1; cvt.u32.u64 %0, t; }"
        : "=r"(a) : "l"(p));
    return a;
}

__device__ __forceinline__ void cp_async16(uint32_t saddr, const void* gaddr) {
    asm volatile("cp.async.cg.shared.global [%0], [%1], 16;\n"
                 :: "r"(saddr), "l"(gaddr) : "memory");
}

__device__ __forceinline__ void ldsm_x4(uint32_t* r, uint32_t addr) {
    asm volatile("ldmatrix.sync.aligned.m8n8.x4.shared.b16 {%0,%1,%2,%3}, [%4];"
                 : "=r"(r[0]), "=r"(r[1]), "=r"(r[2]), "=r"(r[3]) : "r"(addr));
}

__device__ __forceinline__ uint32_t f2tf32(uint32_t bits) {
    uint32_t out;
    asm("cvt.rna.tf32.f32 %0, %1;" : "=r"(out) : "f"(__uint_as_float(bits)));
    return out;
}

__device__ __forceinline__ void mma_tf32(float* c, const uint32_t* a,
                                         uint32_t b0, uint32_t b1) {
    asm volatile(
        "mma.sync.aligned.m16n8k8.row.col.f32.tf32.tf32.f32 "
        "{%0,%1,%2,%3}, {%4,%5,%6,%7}, {%8,%9}, {%0,%1,%2,%3};"
        : "+f"(c[0]), "+f"(c[1]), "+f"(c[2]), "+f"(c[3])
        : "r"(a[0]), "r"(a[1]), "r"(a[2]), "r"(a[3]), "r"(b0), "r"(b1));
}

// ============================ misc helpers ==================================
__device__ __forceinline__ float elu1(float u) {
    return u > 0.0f ? u + 1.0f : __expf(u);
}

__global__ void init_tables() {
    int id = blockIdx.x * blockDim.x + threadIdx.x;
    if (id < 2048) {
        int t = id >> 4;
        int i = id & 15;
        double freq = pow(10.0, -(double)i / 16.0);   // theta^(-4i/hd), theta=10
        double ang = (double)t * freq;
        g_tab[id]        = (float)cos(ang);
        g_tab[2048 + id] = (float)sin(ang);
    }
}

// transpose src[R][Ccols] -> dst[Ccols][R]
__global__ void transpose_k(const float* __restrict__ src, float* __restrict__ dst,
                            int R, int Ccols) {
    __shared__ float tile[32][33];
    int c0 = blockIdx.x * 32, r0 = blockIdx.y * 32;
    for (int i = threadIdx.y; i < 32; i += 8)
        tile[i][threadIdx.x] = src[(long)(r0 + i) * Ccols + c0 + threadIdx.x];
    __syncthreads();
    for (int i = threadIdx.y; i < 32; i += 8)
        dst[(long)(c0 + i) * R + r0 + threadIdx.x] = tile[threadIdx.x][i];
}

// ============ mma.sync TF32 GEMM: 128x128x32 tiles, 3-stage cp.async =========
#define BM 128
#define BN 128
#define BK 32
#define NCHUNK (CDIM / BK)       // 16
#define NSTAGE 3
#define TILE_BYTES 16384          // 128 rows x 128 B
#define STAGE_BYTES 32768         // A tile + B tile
#define SMEM_GEMM (NSTAGE * STAGE_BYTES)   // 98304

// swizzled byte offset for (row, 16B-seg)
__device__ __forceinline__ uint32_t swz(int row, int seg) {
    return (uint32_t)(row * 128 + ((seg ^ (row & 7)) << 4));
}

template<int NS, bool FUSED>
__global__ __launch_bounds__(256, 2)
void mma_gemm(const float* __restrict__ A, const float* __restrict__ Bt,
              const float* __restrict__ bias, float* __restrict__ C) {
    extern __shared__ __align__(1024) char smem[];
    const uint32_t sbase = smem_to_u32(smem);
    const int tid = threadIdx.x;
    const int wid = tid >> 5, lane = tid & 31;
    const int warp_m = wid >> 2;            // 0..1  -> 64 rows each
    const int warp_n = wid & 3;             // 0..3  -> 32 cols each
    const long mBase = (long)blockIdx.y * BM;
    const int  nBase = blockIdx.x * BN;

    // gmem load assignment: 16B seg (tid&7), row (tid>>3) + 32j
    const int segc = tid & 7;
    const int row0 = tid >> 3;
    const float* gA0 = A  + (mBase + row0) * CDIM + segc * 4;
    const float* gB0 = Bt + (long)(nBase + row0) * CDIM + segc * 4;

    float acc[4][4][4];
#pragma unroll
    for (int mt = 0; mt < 4; mt++)
#pragma unroll
        for (int nt = 0; nt < 4; nt++)
#pragma unroll
            for (int q = 0; q < 4; q++) acc[mt][nt][q] = 0.0f;

    // per-thread ldmatrix row constants
    const int arow0 = warp_m * 64 + (lane & 15);          // + mt*16
    const int a_l4  = lane >> 4;                          // seg low bit
    const int brow0 = warp_n * 32 + ((lane >> 4) << 3) + (lane & 7);  // + ntp*16
    const int b_l3  = (lane >> 3) & 1;

    auto compute_stage = [&](int s) {
        const uint32_t as = sbase + s * STAGE_BYTES;
        const uint32_t bs = as + TILE_BYTES;
#pragma unroll
        for (int kk = 0; kk < 4; kk++) {
            uint32_t af[4][4];
#pragma unroll
            for (int mt = 0; mt < 4; mt++) {
                const int r = arow0 + mt * 16;
                ldsm_x4(af[mt], as + swz(r, kk * 2 + a_l4));
            }
            uint32_t bf[2][4];
#pragma unroll
            for (int np = 0; np < 2; np++) {
                const int r = brow0 + np * 16;
                ldsm_x4(bf[np], bs + swz(r, kk * 2 + b_l3));
            }
#pragma unroll
            for (int mt = 0; mt < 4; mt++)
#pragma unroll
                for (int q = 0; q < 4; q++) af[mt][q] = f2tf32(af[mt][q]);
#pragma unroll
            for (int np = 0; np < 2; np++)
#pragma unroll
                for (int q = 0; q < 4; q++) bf[np][q] = f2tf32(bf[np][q]);
#pragma unroll
            for (int mt = 0; mt < 4; mt++)
#pragma unroll
                for (int nt = 0; nt < 4; nt++)
                    mma_tf32(acc[mt][nt], af[mt],
                             bf[nt >> 1][(nt & 1) * 2], bf[nt >> 1][(nt & 1) * 2 + 1]);
        }
    };

    // ---------------- pipelined mainloop ----------------
    for (int kt = 0; kt < NCHUNK; kt++) {
        const uint32_t ss = sbase + (kt % NSTAGE) * STAGE_BYTES;
        const float* ag = gA0 + kt * BK;
        const float* bg = gB0 + kt * BK;
#pragma unroll
        for (int j = 0; j < 4; j++) {
            const uint32_t off = swz(row0 + j * 32, segc);
            cp_async16(ss + off,              ag + (long)j * 32 * CDIM);
            cp_async16(ss + TILE_BYTES + off, bg + (long)j * 32 * CDIM);
        }
        asm volatile("cp.async.commit_group;\n" ::: "memory");
        if (kt >= 2) {
            asm volatile("cp.async.wait_group 2;\n" ::: "memory");
            __syncthreads();
            compute_stage((kt - 2) % NSTAGE);
            __syncthreads();
        }
    }
    asm volatile("cp.async.wait_group 0;\n" ::: "memory");
    __syncthreads();
    compute_stage((NCHUNK - 2) % NSTAGE);
    compute_stage((NCHUNK - 1) % NSTAGE);

    // ---------------- epilogue: bias [+ rope + elu] -> C ----------------
#pragma unroll
    for (int mt = 0; mt < 4; mt++) {
        const long r0g = mBase + warp_m * 64 + mt * 16 + (lane >> 2);
#pragma unroll
        for (int nt = 0; nt < 4; nt++) {
            const int col = nBase + warp_n * 32 + nt * 8 + 2 * (lane & 3);
            const float b0 = bias[col], b1 = bias[col + 1];
            bool plain = true;
            if (FUSED) plain = (col >= 1024);   // v part: no rope/elu
            if (plain) {
#pragma unroll
                for (int hh = 0; hh < 2; hh++) {
                    const long row = r0g + hh * 8;
                    float2 v;
                    v.x = acc[mt][nt][2 * hh]     + b0;
                    v.y = acc[mt][nt][2 * hh + 1] + b1;
                    *(float2*)&C[row * NS + col] = v;
                }
            } else {
                const int d0 = col & 63;
                const int half = (d0 >> 5) & 1;
                const int p = (d0 & 31) >> 1;
#pragma unroll
                for (int hh = 0; hh < 2; hh++) {
                    const long row = r0g + hh * 8;
                    const int n = (int)(row & (SEQ - 1));
                    const int t = half ? (n >> 7) : (n & 127);
                    const float cc = g_tab[t * 16 + p];
                    const float sn = g_tab[2048 + t * 16 + p];
                    const float xr = acc[mt][nt][2 * hh]     + b0;
                    const float xi = acc[mt][nt][2 * hh + 1] + b1;
                    float2 v;
                    v.x = elu1(xr * cc - xi * sn);
                    v.y = elu1(xr * sn + xi * cc);
                    *(float2*)&C[row * NS + col] = v;
                }
            }
        }
    }
}

// ---------------- KV / ksum partial reduction ----------------
__global__ __launch_bounds__(256)
void kv_partial() {
    const int chunk = blockIdx.x;
    const int bh = blockIdx.y;
    const int b = bh >> 3, h = bh & 7;
    const int tid = threadIdx.x;
    const int d  = tid & 63;
    const int e0 = (tid >> 6) << 4;
    const int lr = tid >> 6;
    const int ld = tid & 63;

    __shared__ float ks[4][64];
    __shared__ float vs[4][64];

    float acc[16];
#pragma unroll
    for (int e = 0; e < 16; e++) acc[e] = 0.0f;
    float ksacc = 0.0f;

    const long base = (long)(b * SEQ + chunk * 256) * N1 + h * 64;
    const float* Kp = g_qkv + base + 512;
    const float* Vp = g_qkv + base + 1024;

    for (int g = 0; g < 256; g += 4) {
        ks[lr][ld] = Kp[(long)(g + lr) * N1 + ld];
        vs[lr][ld] = Vp[(long)(g + lr) * N1 + ld];
        __syncthreads();
#pragma unroll
        for (int r = 0; r < 4; r++) {
            float kd = ks[r][d];
            if (tid < 64) ksacc += kd;
            const float* vr = &vs[r][e0];
#pragma unroll
            for (int e = 0; e < 16; e++) acc[e] += kd * vr[e];
        }
        __syncthreads();
    }

    float* out = g_kvp + ((long)(bh * 64 + chunk)) * 4096 + d * 64 + e0;
#pragma unroll
    for (int e = 0; e < 16; e++) out[e] = acc[e];
    if (tid < 64) g_ksp[(bh * 64 + chunk) * 64 + tid] = ksacc;
}

__global__ void kv_reduce() {
    int gid = blockIdx.x * 256 + threadIdx.x;
    if (gid < 32 * 4096) {
        int bh = gid >> 12;
        int rem = gid & 4095;
        const float* p = g_kvp + (long)bh * 64 * 4096 + rem;
        float s = 0.0f;
#pragma unroll 8
        for (int c = 0; c < 64; c++) s += p[(long)c * 4096];
        g_kv[gid] = s;
    } else {
        int idx = gid - 32 * 4096;
        if (idx < 2048) {
            int bh = idx >> 6, dd = idx & 63;
            const float* p = g_ksp + bh * 64 * 64 + dd;
            float s = 0.0f;
#pragma unroll 8
            for (int c = 0; c < 64; c++) s += p[c * 64];
            g_ksum[idx] = s;
        }
    }
}

// ---------------- apply: out = (q @ KV) * 1/(q.ksum + 1e-6) ----------------
__global__ __launch_bounds__(256)
void apply_kernel() {
    const int chunk = blockIdx.x;
    const int bh = blockIdx.y;
    const int b = bh >> 3, h = bh & 7;
    const int tid = threadIdx.x;

    __shared__ float kv_sh[4096];
    __shared__ float ks_sh[64];
    for (int i = tid; i < 4096; i += 256) kv_sh[i] = g_kv[bh * 4096 + i];
    if (tid < 64) ks_sh[tid] = g_ksum[bh * 64 + tid];
    __syncthreads();

    const int n = chunk * 256 + tid;
    const float* qp = g_qkv + (long)(b * SEQ + n) * N1 + h * 64;
    float q[64];
#pragma unroll
    for (int i = 0; i < 16; i++)
        *(float4*)&q[i * 4] = *(const float4*)&qp[i * 4];

    float denom = 0.0f;
#pragma unroll
    for (int d = 0; d < 64; d++) denom += q[d] * ks_sh[d];
    float z = 1.0f / (denom + 1e-6f);

    float* op = g_attn + (long)(b * SEQ + n) * N2 + h * 64;
#pragma unroll
    for (int eh = 0; eh < 64; eh += 32) {
        float o[32];
#pragma unroll
        for (int e = 0; e < 32; e++) o[e] = 0.0f;
#pragma unroll 4
        for (int d = 0; d < 64; d++) {
            float qd = q[d];
            const float* kr = &kv_sh[d * 64 + eh];
#pragma unroll
            for (int e = 0; e < 32; e++) o[e] += qd * kr[e];
        }
#pragma unroll
        for (int e = 0; e < 32; e += 4) {
            float4 v4;
            v4.x = o[e] * z; v4.y = o[e + 1] * z;
            v4.z = o[e + 2] * z; v4.w = o[e + 3] * z;
            *(float4*)&op[eh + e] = v4;
        }
    }
}

// ---------------- launch ----------------
extern "C" void kernel_launch(void* const* d_in, const int* in_sizes, int n_in,
                              void* d_out, int out_size) {
    (void)in_sizes; (void)n_in; (void)out_size;
    const float* x      = (const float*)d_in[0];
    const float* w_qkv  = (const float*)d_in[1];
    const float* b_qkv  = (const float*)d_in[2];
    const float* w_proj = (const float*)d_in[3];
    const float* b_proj = (const float*)d_in[4];
    float* out = (float*)d_out;

    float *p_qkv = nullptr, *p_attn = nullptr, *p_bt1 = nullptr, *p_bt2 = nullptr;
    cudaGetSymbolAddress((void**)&p_qkv,  g_qkv);
    cudaGetSymbolAddress((void**)&p_attn, g_attn);
    cudaGetSymbolAddress((void**)&p_bt1,  g_bt1);
    cudaGetSymbolAddress((void**)&p_bt2,  g_bt2);

    cudaFuncSetAttribute((const void*)mma_gemm<N1, true>,
                         cudaFuncAttributeMaxDynamicSharedMemorySize, SMEM_GEMM);
    cudaFuncSetAttribute((const void*)mma_gemm<N2, false>,
                         cudaFuncAttributeMaxDynamicSharedMemorySize, SMEM_GEMM);

    init_tables<<<8, 256>>>();
    transpose_k<<<dim3(N1 / 32, CDIM / 32), dim3(32, 8)>>>(w_qkv,  p_bt1, CDIM, N1);
    transpose_k<<<dim3(N2 / 32, CDIM / 32), dim3(32, 8)>>>(w_proj, p_bt2, CDIM, N2);

    // QKV GEMM (tf32 mma.sync) + bias + rope + elu+1 fused
    mma_gemm<N1, true><<<dim3(N1 / BN, MTOT / BM), 256, SMEM_GEMM>>>(
        x, p_bt1, b_qkv, p_qkv);

    // KV / ksum reduction (two-phase, deterministic)
    kv_partial<<<dim3(64, 32), 256>>>();
    kv_reduce<<<520, 256>>>();

    // apply attention
    apply_kernel<<<dim3(64, 32), 256>>>();

    // projection GEMM (tf32 mma.sync) + bias
    mma_gemm<N2, false><<<dim3(N2 / BN, MTOT / BM), 256, SMEM_GEMM>>>(
        p_attn, p_bt2, b_proj, out);
}